// round 4
// baseline (speedup 1.0000x reference)
#include <cuda_runtime.h>
#include <stdint.h>

// Problem constants
#define NB   8
#define CIN  3
#define HW   128
#define OC   16
#define NF   27          // Cin*3*3

// Device scratch: two half-tables, 16B rows (8 channels each).
// Row stride 16B -> LDS.128 start slot = idx mod 8 -> 8 distinct 16B slots.
__device__ __align__(16) short g_prodA[NF*256*8];   // [f][ip][o:0-7]   108KB
__device__ __align__(16) short g_prodB[NF*256*8];   // [f][ip][o:8-15]  108KB

// ---------------------------------------------------------------------------
// Table builder: one thread per (f, ip, o). Quantizes its weight inline,
// gathers lut pair, writes combined int16 product into the split tables.
// ---------------------------------------------------------------------------
__global__ void prep_table(const float* __restrict__ w,
                           const float* __restrict__ swp,
                           const int*   __restrict__ lut)
{
    int idx = blockIdx.x * blockDim.x + threadIdx.x;   // 27*256*16 = 110592
    if (idx >= NF*256*OC) return;
    int o  = idx & 15;
    int ip = (idx >> 4) & 255;
    int f  = idx >> 12;

    float q = rintf(w[o*NF + f] / swp[0]);   // round-half-even like jnp.round
    q = fminf(fmaxf(q, -127.0f), 127.0f);
    int iw = (int)q + 128;

    int row = ip*256 + iw;
    int2 hl = ((const int2*)lut)[row];       // (hi, lo)
    short v = (short)(hl.x*256 + (hl.y & 255));

    if (o < 8) g_prodA[(f*256 + ip)*8 + o]     = v;
    else       g_prodB[(f*256 + ip)*8 + (o-8)] = v;
}

// ---------------------------------------------------------------------------
// Conv: 128 blocks x 1024 threads = 1 thread per (b,h,w) pixel, one wave.
// SMEM: 2x108KB split tables + 3x10x130 quantized activation tile.
// Fully-unrolled 27-tap loop so ptxas can pipeline LDS across taps.
// hi-halfword extraction via IMAD.HI (fma pipe), lo via SGXT (alu pipe).
// ---------------------------------------------------------------------------
#define SM_A_BYTES   (NF*256*8*2)        // 110592
#define SM_AB_BYTES  (2*SM_A_BYTES)      // 221184
#define SM_TILE_ELEMS (3*10*130)         // 3900
#define SM_TOTAL     (SM_AB_BYTES + ((SM_TILE_ELEMS + 15) & ~15))

__device__ __forceinline__ int lo16(unsigned v) { return (int)(short)(v & 0xFFFFu); }   // SGXT (alu)
__device__ __forceinline__ int hi16(unsigned v) { return __mulhi((int)v, 65536); }      // IMAD.HI (fma)

__global__ __launch_bounds__(1024)
void conv_kernel(const float* __restrict__ x,
                 const float* __restrict__ bias,
                 const float* __restrict__ sxp,
                 const float* __restrict__ swp,
                 float* __restrict__ out)
{
    extern __shared__ char smem[];
    unsigned char* stile = (unsigned char*)(smem + SM_AB_BYTES);

    const int tid  = threadIdx.x;
    const int b    = blockIdx.x >> 4;   // batch
    const int rowg = blockIdx.x & 15;   // 8-row group within image

    // Hoist bias into registers before the crunch
    float4 bias_lo = ((const float4*)bias)[0];
    float4 bias_mi = ((const float4*)bias)[1];
    float4 bias_hi = ((const float4*)bias)[2];
    float4 bias_tp = ((const float4*)bias)[3];

    // Stage both half-tables (216KB) with int4 vector copies
    {
        const int4* srcA = (const int4*)g_prodA;
        const int4* srcB = (const int4*)g_prodB;
        int4* dstA = (int4*)smem;
        int4* dstB = (int4*)(smem + SM_A_BYTES);
        #pragma unroll
        for (int k = 0; k < 6; k++) {
            dstA[tid + k*1024] = srcA[tid + k*1024];
            dstB[tid + k*1024] = srcB[tid + k*1024];
        }
        if (tid < (SM_A_BYTES/16 - 6*1024)) {           // 6912 - 6144 = 768
            dstA[tid + 6*1024] = srcA[tid + 6*1024];
            dstB[tid + 6*1024] = srcB[tid + 6*1024];
        }
    }

    // Stage + quantize activation tile [3][10][130]; out-of-image -> ip=128
    {
        const float sx = sxp[0];
        for (int t = tid; t < SM_TILE_ELEMS; t += 1024) {
            int cin = t / 1300;
            int rem = t - cin*1300;
            int rr  = rem / 130;
            int cc  = rem - rr*130;
            int hh  = rowg*8 + rr - 1;
            int ww  = cc - 1;
            unsigned char v = 128;
            if ((unsigned)hh < 128u && (unsigned)ww < 128u) {
                float xf = x[((b*3 + cin)*128 + hh)*128 + ww];
                float q = rintf(xf / sx);                 // round-half-even
                q = fminf(fmaxf(q, -127.0f), 127.0f);
                v = (unsigned char)((int)q + 128);
            }
            stile[t] = v;
        }
    }
    __syncthreads();

    const int c = tid & 127;   // column
    const int r = tid >> 7;    // row within 8-row group

    int acc[OC];
    #pragma unroll
    for (int o = 0; o < OC; o++) acc[o] = 0;

    const uint4* TA = (const uint4*)smem;
    const uint4* TB = (const uint4*)(smem + SM_A_BYTES);
    const unsigned char* tbase = &stile[r*130 + c];

    // Fully unrolled 27 taps: no unroll-1 fences, ptxas pipelines the LDS
    #pragma unroll
    for (int cin = 0; cin < 3; cin++) {
        #pragma unroll
        for (int dh = 0; dh < 3; dh++) {
            const unsigned char* trow = tbase + cin*1300 + dh*130;
            #pragma unroll
            for (int dw = 0; dw < 3; dw++) {
                const int f   = (cin*3 + dh)*3 + dw;
                const int idx = f*256 + (int)trow[dw];
                uint4 a  = TA[idx];
                uint4 bq = TB[idx];
                acc[ 0] += lo16(a.x);  acc[ 1] += hi16(a.x);
                acc[ 2] += lo16(a.y);  acc[ 3] += hi16(a.y);
                acc[ 4] += lo16(a.z);  acc[ 5] += hi16(a.z);
                acc[ 6] += lo16(a.w);  acc[ 7] += hi16(a.w);
                acc[ 8] += lo16(bq.x); acc[ 9] += hi16(bq.x);
                acc[10] += lo16(bq.y); acc[11] += hi16(bq.y);
                acc[12] += lo16(bq.z); acc[13] += hi16(bq.z);
                acc[14] += lo16(bq.w); acc[15] += hi16(bq.w);
            }
        }
    }

    const float s = sxp[0] * swp[0];
    const int h = rowg*8 + r;
    float* obase = &out[(b*OC*128 + h)*128 + c];
    const float bb[OC] = { bias_lo.x, bias_lo.y, bias_lo.z, bias_lo.w,
                           bias_mi.x, bias_mi.y, bias_mi.z, bias_mi.w,
                           bias_hi.x, bias_hi.y, bias_hi.z, bias_hi.w,
                           bias_tp.x, bias_tp.y, bias_tp.z, bias_tp.w };
    #pragma unroll
    for (int o = 0; o < OC; o++)
        obase[o*128*128] = (float)acc[o] * s + bb[o];
}

// ---------------------------------------------------------------------------
extern "C" void kernel_launch(void* const* d_in, const int* in_sizes, int n_in,
                              void* d_out, int out_size)
{
    const float* x    = (const float*)d_in[0];
    const float* w    = (const float*)d_in[1];
    const float* bias = (const float*)d_in[2];
    const float* sx   = (const float*)d_in[3];
    const float* sw   = (const float*)d_in[4];
    const int*   lut  = (const int*)d_in[5];
    float* out = (float*)d_out;

    cudaFuncSetAttribute(conv_kernel,
                         cudaFuncAttributeMaxDynamicSharedMemorySize, SM_TOTAL);

    prep_table<<<(NF*256*OC + 255) / 256, 256>>>(w, sw, lut);
    conv_kernel<<<NB * 16, 1024, SM_TOTAL>>>(x, bias, sx, sw, out);
}

// round 5
// speedup vs baseline: 1.0904x; 1.0904x over previous
#include <cuda_runtime.h>
#include <stdint.h>

// Problem constants
#define NB   8
#define CIN  3
#define HW   128
#define OC   16
#define NF   27          // Cin*3*3

// Device scratch: two half-tables, 16B rows (8 channels each).
__device__ __align__(16) short g_prodA[NF*256*8];   // [f][ip][o:0-7]   108KB
__device__ __align__(16) short g_prodB[NF*256*8];   // [f][ip][o:8-15]  108KB

// ---------------------------------------------------------------------------
// Table builder: one thread per (f, ip, o). Quantizes its weight inline,
// gathers lut pair, writes combined int16 product into the split tables.
// ---------------------------------------------------------------------------
__global__ void prep_table(const float* __restrict__ w,
                           const float* __restrict__ swp,
                           const int*   __restrict__ lut)
{
    int idx = blockIdx.x * blockDim.x + threadIdx.x;   // 27*256*16 = 110592
    if (idx >= NF*256*OC) return;
    int o  = idx & 15;
    int ip = (idx >> 4) & 255;
    int f  = idx >> 12;

    float q = rintf(w[o*NF + f] / swp[0]);   // round-half-even like jnp.round
    q = fminf(fmaxf(q, -127.0f), 127.0f);
    int iw = (int)q + 128;

    int row = ip*256 + iw;
    int2 hl = ((const int2*)lut)[row];       // (hi, lo)
    short v = (short)(hl.x*256 + (hl.y & 255));

    if (o < 8) g_prodA[(f*256 + ip)*8 + o]     = v;
    else       g_prodB[(f*256 + ip)*8 + (o-8)] = v;
}

// ---------------------------------------------------------------------------
// Conv: 128 blocks x 1024 threads = 1 thread per (b,h,w) pixel, one wave.
// Flat 27-tap loop, manual 1-tap-ahead software prefetch (bounded regs),
// lo16 on alu pipe (SGXT), hi16 on fma pipe (IMAD.HI).
// ---------------------------------------------------------------------------
#define SM_A_BYTES    (NF*256*8*2)       // 110592
#define SM_AB_BYTES   (2*SM_A_BYTES)     // 221184
#define SM_TILE_BYTES ((3*10*130 + 15) & ~15)   // 3904
#define SM_OFF_OFF    (SM_AB_BYTES + SM_TILE_BYTES)
#define SM_TOTAL      (SM_OFF_OFF + 28*4)

__device__ __forceinline__ int lo16(unsigned v) { return (int)(short)(v & 0xFFFFu); }   // SGXT (alu)
__device__ __forceinline__ int hi16(unsigned v) { return __mulhi((int)v, 65536); }      // IMAD.HI (fma)

__global__ __launch_bounds__(1024)
void conv_kernel(const float* __restrict__ x,
                 const float* __restrict__ bias,
                 const float* __restrict__ sxp,
                 const float* __restrict__ swp,
                 float* __restrict__ out)
{
    extern __shared__ char smem[];
    unsigned char* stile = (unsigned char*)(smem + SM_AB_BYTES);
    int*           soff  = (int*)(smem + SM_OFF_OFF);

    const int tid  = threadIdx.x;
    const int b    = blockIdx.x >> 4;   // batch
    const int rowg = blockIdx.x & 15;   // 8-row group within image

    // Stage both half-tables (216KB) with int4 vector copies
    {
        const int4* srcA = (const int4*)g_prodA;
        const int4* srcB = (const int4*)g_prodB;
        int4* dstA = (int4*)smem;
        int4* dstB = (int4*)(smem + SM_A_BYTES);
        #pragma unroll
        for (int k = 0; k < 6; k++) {
            dstA[tid + k*1024] = srcA[tid + k*1024];
            dstB[tid + k*1024] = srcB[tid + k*1024];
        }
        if (tid < (SM_A_BYTES/16 - 6*1024)) {           // 768 remaining
            dstA[tid + 6*1024] = srcA[tid + 6*1024];
            dstB[tid + 6*1024] = srcB[tid + 6*1024];
        }
    }

    // Tap offset table (28 entries; last duplicates f=26 for safe prefetch)
    if (tid < 28) {
        int f   = (tid < 27) ? tid : 26;
        int cin = f / 9;
        int rem = f - cin*9;
        int dh  = rem / 3;
        int dw  = rem - dh*3;
        soff[tid] = cin*1300 + dh*130 + dw;
    }

    // Stage + quantize activation tile [3][10][130]; out-of-image -> ip=128
    {
        const float sx = sxp[0];
        for (int t = tid; t < 3*10*130; t += 1024) {
            int cin = t / 1300;
            int rem = t - cin*1300;
            int rr  = rem / 130;
            int cc  = rem - rr*130;
            int hh  = rowg*8 + rr - 1;
            int ww  = cc - 1;
            unsigned char v = 128;
            if ((unsigned)hh < 128u && (unsigned)ww < 128u) {
                float xf = x[((b*3 + cin)*128 + hh)*128 + ww];
                float q = rintf(xf / sx);                 // round-half-even
                q = fminf(fmaxf(q, -127.0f), 127.0f);
                v = (unsigned char)((int)q + 128);
            }
            stile[t] = v;
        }
    }
    __syncthreads();

    const int c = tid & 127;   // column
    const int r = tid >> 7;    // row within 8-row group

    int acc[OC];
    #pragma unroll
    for (int o = 0; o < OC; o++) acc[o] = 0;

    const uint4* TA = (const uint4*)smem;
    const uint4* TB = (const uint4*)(smem + SM_A_BYTES);
    const unsigned char* tb = &stile[r*130 + c];

    // Software-pipelined 27-tap loop: prefetch tap f+1 before consuming tap f
    int idx0 = (int)tb[soff[0]];            // f=0 row index (0*256 + ip)
    uint4 a  = TA[idx0];
    uint4 bq = TB[idx0];

    #pragma unroll 3
    for (int f = 0; f < 27; f++) {
        int fn   = (f < 26) ? f + 1 : 26;   // clamp: last iter re-reads f=26
        int idxn = fn*256 + (int)tb[soff[fn]];
        uint4 an  = TA[idxn];
        uint4 bn  = TB[idxn];

        acc[ 0] += lo16(a.x);  acc[ 1] += hi16(a.x);
        acc[ 2] += lo16(a.y);  acc[ 3] += hi16(a.y);
        acc[ 4] += lo16(a.z);  acc[ 5] += hi16(a.z);
        acc[ 6] += lo16(a.w);  acc[ 7] += hi16(a.w);
        acc[ 8] += lo16(bq.x); acc[ 9] += hi16(bq.x);
        acc[10] += lo16(bq.y); acc[11] += hi16(bq.y);
        acc[12] += lo16(bq.z); acc[13] += hi16(bq.z);
        acc[14] += lo16(bq.w); acc[15] += hi16(bq.w);

        a = an; bq = bn;
    }

    const float s = sxp[0] * swp[0];
    const int h = rowg*8 + r;
    float* obase = &out[(b*OC*128 + h)*128 + c];
    #pragma unroll
    for (int o = 0; o < OC; o++)
        obase[o*128*128] = (float)acc[o] * s + __ldg(&bias[o]);
}

// ---------------------------------------------------------------------------
extern "C" void kernel_launch(void* const* d_in, const int* in_sizes, int n_in,
                              void* d_out, int out_size)
{
    const float* x    = (const float*)d_in[0];
    const float* w    = (const float*)d_in[1];
    const float* bias = (const float*)d_in[2];
    const float* sx   = (const float*)d_in[3];
    const float* sw   = (const float*)d_in[4];
    const int*   lut  = (const int*)d_in[5];
    float* out = (float*)d_out;

    cudaFuncSetAttribute(conv_kernel,
                         cudaFuncAttributeMaxDynamicSharedMemorySize, SM_TOTAL);

    prep_table<<<(NF*256*OC + 255) / 256, 256>>>(w, sw, lut);
    conv_kernel<<<NB * 16, 1024, SM_TOTAL>>>(x, bias, sx, sw, out);
}

// round 6
// speedup vs baseline: 1.1951x; 1.0960x over previous
#include <cuda_runtime.h>
#include <stdint.h>

// Problem constants
#define NB   8
#define CIN  3
#define HW   128
#define OC   16
#define NF   27          // Cin*3*3

// Device scratch: two half-tables, 16B rows (8 channels each).
__device__ __align__(16) short g_prodA[NF*256*8];   // [f][ip][o:0-7]   108KB
__device__ __align__(16) short g_prodB[NF*256*8];   // [f][ip][o:8-15]  108KB

// ---------------------------------------------------------------------------
// Table builder: one thread per (f, ip, o). Quantizes its weight inline,
// gathers lut pair, writes combined int16 product into the split tables.
// ---------------------------------------------------------------------------
__global__ void prep_table(const float* __restrict__ w,
                           const float* __restrict__ swp,
                           const int*   __restrict__ lut)
{
    int idx = blockIdx.x * blockDim.x + threadIdx.x;   // 27*256*16 = 110592
    if (idx >= NF*256*OC) return;
    int o  = idx & 15;
    int ip = (idx >> 4) & 255;
    int f  = idx >> 12;

    float q = rintf(w[o*NF + f] / swp[0]);   // round-half-even like jnp.round
    q = fminf(fmaxf(q, -127.0f), 127.0f);
    int iw = (int)q + 128;

    int row = ip*256 + iw;
    int2 hl = ((const int2*)lut)[row];       // (hi, lo)
    short v = (short)(hl.x*256 + (hl.y & 255));

    if (o < 8) g_prodA[(f*256 + ip)*8 + o]     = v;
    else       g_prodB[(f*256 + ip)*8 + (o-8)] = v;
}

// ---------------------------------------------------------------------------
// Conv: 256 blocks x 1024 threads, TWO blocks per SM (channel halves).
// Each block: one 108KB half-table + 3.9KB tile in SMEM, 8 output channels.
// 2048 threads/SM -> 16 warps/SMSP for latency hiding.
// ---------------------------------------------------------------------------
#define SM_A_BYTES    (NF*256*8*2)              // 110592
#define SM_TILE_BYTES ((3*10*130 + 15) & ~15)   // 3904
#define SM_TOTAL      (SM_A_BYTES + SM_TILE_BYTES)

__device__ __forceinline__ int lo16(unsigned v) { return (int)(short)(v & 0xFFFFu); }   // alu pipe
__device__ __forceinline__ int hi16(unsigned v) { return __mulhi((int)v, 65536); }      // fma pipe

__global__ __launch_bounds__(1024, 2)
void conv_kernel(const float* __restrict__ x,
                 const float* __restrict__ bias,
                 const float* __restrict__ sxp,
                 const float* __restrict__ swp,
                 float* __restrict__ out)
{
    extern __shared__ char smem[];
    unsigned char* stile = (unsigned char*)(smem + SM_A_BYTES);

    const int tid  = threadIdx.x;
    const int half = blockIdx.x & 1;          // channel half: 0 -> o 0-7, 1 -> o 8-15
    const int rest = blockIdx.x >> 1;
    const int b    = rest >> 4;               // batch
    const int rowg = rest & 15;               // 8-row group within image

    // Stage this block's 108KB half-table (int4 vector copies)
    {
        const int4* src = half ? (const int4*)g_prodB : (const int4*)g_prodA;
        int4* dst = (int4*)smem;
        #pragma unroll
        for (int k = 0; k < 6; k++)
            dst[tid + k*1024] = src[tid + k*1024];
        if (tid < (SM_A_BYTES/16 - 6*1024))   // 768 remaining
            dst[tid + 6*1024] = src[tid + 6*1024];
    }

    // Stage + quantize activation tile [3][10][130]; out-of-image -> ip=128
    {
        const float sx = sxp[0];
        for (int t = tid; t < 3*10*130; t += 1024) {
            int cin = t / 1300;
            int rem = t - cin*1300;
            int rr  = rem / 130;
            int cc  = rem - rr*130;
            int hh  = rowg*8 + rr - 1;
            int ww  = cc - 1;
            unsigned char v = 128;
            if ((unsigned)hh < 128u && (unsigned)ww < 128u) {
                float xf = x[((b*3 + cin)*128 + hh)*128 + ww];
                float q = rintf(xf / sx);                 // round-half-even
                q = fminf(fmaxf(q, -127.0f), 127.0f);
                v = (unsigned char)((int)q + 128);
            }
            stile[t] = v;
        }
    }
    __syncthreads();

    const int c = tid & 127;   // column
    const int r = tid >> 7;    // row within 8-row group

    int acc[8];
    #pragma unroll
    for (int o = 0; o < 8; o++) acc[o] = 0;

    const uint4* TA = (const uint4*)smem;
    const unsigned char* tb = &stile[r*130 + c];

    #pragma unroll 1
    for (int cin = 0; cin < 3; cin++) {
        // Load all 9 tile bytes for this input channel first (independent LDS,
        // breaks the byte->index->table dependent chain)
        int ipx[9];
        #pragma unroll
        for (int dh = 0; dh < 3; dh++)
            #pragma unroll
            for (int dw = 0; dw < 3; dw++)
                ipx[dh*3 + dw] = (int)tb[cin*1300 + dh*130 + dw];

        // 9 straight-line taps; ptxas pipelines the LDS.128s under reg budget
        #pragma unroll
        for (int t = 0; t < 9; t++) {
            uint4 v = TA[(cin*9 + t)*256 + ipx[t]];
            acc[0] += lo16(v.x);  acc[1] += hi16(v.x);
            acc[2] += lo16(v.y);  acc[3] += hi16(v.y);
            acc[4] += lo16(v.z);  acc[5] += hi16(v.z);
            acc[6] += lo16(v.w);  acc[7] += hi16(v.w);
        }
    }

    const float s = sxp[0] * swp[0];
    const int h = rowg*8 + r;
    float* obase = &out[((b*OC + half*8)*128 + h)*128 + c];
    #pragma unroll
    for (int o = 0; o < 8; o++)
        obase[o*128*128] = (float)acc[o] * s + __ldg(&bias[half*8 + o]);
}

// ---------------------------------------------------------------------------
extern "C" void kernel_launch(void* const* d_in, const int* in_sizes, int n_in,
                              void* d_out, int out_size)
{
    const float* x    = (const float*)d_in[0];
    const float* w    = (const float*)d_in[1];
    const float* bias = (const float*)d_in[2];
    const float* sx   = (const float*)d_in[3];
    const float* sw   = (const float*)d_in[4];
    const int*   lut  = (const int*)d_in[5];
    float* out = (float*)d_out;

    cudaFuncSetAttribute(conv_kernel,
                         cudaFuncAttributeMaxDynamicSharedMemorySize, SM_TOTAL);

    prep_table<<<(NF*256*OC + 255) / 256, 256>>>(w, sw, lut);
    conv_kernel<<<NB * 16 * 2, 1024, SM_TOTAL>>>(x, bias, sx, sw, out);
}